// round 1
// baseline (speedup 1.0000x reference)
#include <cuda_runtime.h>
#include <cstdint>

// Problem constants
#define Bn 64
#define Sn 512
#define Nn 128
#define Dn 768
#define On 3

// Scratch (device globals -- no allocations allowed)
__device__ float g_x[(size_t)Bn * Nn * Dn];      // node features (in-place across layers)
__device__ float g_t[(size_t)Bn * Nn * Dn];      // tmps / h@W temporary
__device__ float g_adj[(size_t)Bn * Nn * Nn];    // clamped adjacency
__device__ float g_denom[(size_t)Bn * Nn];       // row-degree + 1e-7
__device__ float g_tmax[(size_t)Bn * Dn];        // target max-pool

// ---------------------------------------------------------------------------
// adjacency: adj = min(dg+dg1, 1); denom = rowsum + 1e-7
// ---------------------------------------------------------------------------
__global__ void adj_kernel(const float* __restrict__ dg, const float* __restrict__ dg1) {
    int row = blockIdx.x;           // b*N + n
    int tid = threadIdx.x;          // 128 threads
    float a = dg[(size_t)row * Nn + tid] + dg1[(size_t)row * Nn + tid];
    a = fminf(a, 1.0f);
    g_adj[(size_t)row * Nn + tid] = a;
    __shared__ float s[128];
    s[tid] = a;
    __syncthreads();
    #pragma unroll
    for (int st = 64; st > 0; st >>= 1) {
        if (tid < st) s[tid] += s[tid + st];
        __syncthreads();
    }
    if (tid == 0) g_denom[row] = s[0] + 1e-7f;
}

// ---------------------------------------------------------------------------
// tran span sums: tmps[b,n,:] = sum_{s in [s0+1, e0+1)} se[b,s,:]  -> g_t
// ---------------------------------------------------------------------------
__global__ void span_kernel(const float* __restrict__ se, const int* __restrict__ tran) {
    int row = blockIdx.x;           // b*N + n
    int b = row >> 7;
    int s0 = tran[row * 2] + 1;
    int e0 = tran[row * 2 + 1] + 1;
    for (int d = threadIdx.x; d < Dn; d += 256) {
        float acc = 0.0f;
        for (int s = s0; s < e0; ++s)
            acc += se[((size_t)b * Sn + s) * Dn + d];
        g_t[(size_t)row * Dn + d] = acc;
    }
}

// ---------------------------------------------------------------------------
// target max-pool over [l, r)
// ---------------------------------------------------------------------------
__global__ void tmax_kernel(const float* __restrict__ se, const int* __restrict__ tspan) {
    int b = blockIdx.x;
    int l = tspan[b * 2];
    int r = tspan[b * 2 + 1];
    for (int d = threadIdx.x; d < Dn; d += 256) {
        float m = -3.402823466e38f;
        for (int s = l; s < r; ++s)
            m = fmaxf(m, se[((size_t)b * Sn + s) * Dn + d]);
        g_tmax[(size_t)b * Dn + d] = m;
    }
}

// ---------------------------------------------------------------------------
// SGEMM: C[M,N] = act(A[M,K] @ W[K,N]); M=8192, N=K=768
// 128x128 block tile, BK=16, 256 threads, 8x8 per-thread microtile
// ---------------------------------------------------------------------------
template <bool RELU>
__global__ void sgemm_kernel(const float* __restrict__ A, const float* __restrict__ W,
                             float* __restrict__ C, int M, int Ncols, int K) {
    __shared__ float As[16][128];
    __shared__ float Bs[16][128];
    int tid = threadIdx.x;
    int bm = blockIdx.y * 128;
    int bn = blockIdx.x * 128;
    int tx = tid % 16, ty = tid / 16;

    float acc[8][8];
    #pragma unroll
    for (int i = 0; i < 8; ++i)
        #pragma unroll
        for (int j = 0; j < 8; ++j) acc[i][j] = 0.0f;

    int aRow = tid / 4;             // 0..63
    int aCol = (tid % 4) * 4;       // 0,4,8,12
    int bRow = tid / 32;            // 0..7
    int bCol = (tid % 32) * 4;      // 0..124

    for (int k0 = 0; k0 < K; k0 += 16) {
        #pragma unroll
        for (int r = 0; r < 2; ++r) {
            float4 a4 = *(const float4*)&A[(size_t)(bm + aRow + r * 64) * K + k0 + aCol];
            As[aCol + 0][aRow + r * 64] = a4.x;
            As[aCol + 1][aRow + r * 64] = a4.y;
            As[aCol + 2][aRow + r * 64] = a4.z;
            As[aCol + 3][aRow + r * 64] = a4.w;
        }
        #pragma unroll
        for (int r = 0; r < 2; ++r) {
            float4 b4 = *(const float4*)&W[(size_t)(k0 + bRow + r * 8) * Ncols + bn + bCol];
            *(float4*)&Bs[bRow + r * 8][bCol] = b4;
        }
        __syncthreads();
        #pragma unroll
        for (int kk = 0; kk < 16; ++kk) {
            float ra[8], rb[8];
            #pragma unroll
            for (int i = 0; i < 8; ++i) ra[i] = As[kk][ty * 8 + i];
            #pragma unroll
            for (int j = 0; j < 8; ++j) rb[j] = Bs[kk][tx * 8 + j];
            #pragma unroll
            for (int i = 0; i < 8; ++i)
                #pragma unroll
                for (int j = 0; j < 8; ++j)
                    acc[i][j] += ra[i] * rb[j];
        }
        __syncthreads();
    }

    #pragma unroll
    for (int i = 0; i < 8; ++i) {
        size_t row = (size_t)(bm + ty * 8 + i);
        #pragma unroll
        for (int j = 0; j < 8; j += 4) {
            float4 v;
            v.x = acc[i][j + 0];
            v.y = acc[i][j + 1];
            v.z = acc[i][j + 2];
            v.w = acc[i][j + 3];
            if (RELU) {
                v.x = fmaxf(v.x, 0.0f); v.y = fmaxf(v.y, 0.0f);
                v.z = fmaxf(v.z, 0.0f); v.w = fmaxf(v.w, 0.0f);
            }
            *(float4*)&C[row * Ncols + bn + tx * 8 + j] = v;
        }
    }
}

// ---------------------------------------------------------------------------
// GCN aggregation: x = relu(adj@t / denom + bias) + x   (adj rows sparse 0/1)
// one block per (b,n) row; gather nonzero columns first
// ---------------------------------------------------------------------------
__global__ void adj_spmm_kernel(const float* __restrict__ bias) {
    int row = blockIdx.x;           // b*N + n
    int b = row >> 7;
    int tid = threadIdx.x;          // 256
    __shared__ float av[Nn];
    __shared__ int   aidx[Nn];
    __shared__ int   s_nnz;
    if (tid == 0) s_nnz = 0;
    __syncthreads();
    if (tid < Nn) {
        float v = g_adj[(size_t)row * Nn + tid];
        if (v != 0.0f) {
            int p = atomicAdd(&s_nnz, 1);
            av[p] = v;
            aidx[p] = tid;
        }
    }
    __syncthreads();
    int nnz = s_nnz;
    float den = g_denom[row];
    const float* tb = g_t + (size_t)b * Nn * Dn;
    for (int d = tid; d < Dn; d += 256) {
        float acc = 0.0f;
        for (int i = 0; i < nnz; ++i)
            acc += av[i] * tb[(size_t)aidx[i] * Dn + d];
        float y = acc / den + bias[d];
        size_t o = (size_t)row * Dn + d;
        g_x[o] = fmaxf(y, 0.0f) + g_x[o];
    }
}

// ---------------------------------------------------------------------------
// head: gcn_target (node-span sum) + concat + fc + tanh
// ---------------------------------------------------------------------------
__global__ void head_kernel(const float* __restrict__ fcW, const float* __restrict__ fcb,
                            const int* __restrict__ gspan, float* __restrict__ out) {
    int b = blockIdx.x;
    int tid = threadIdx.x;          // 256
    int gs = gspan[b * 2];
    int ge = gspan[b * 2 + 1];
    float p0 = 0.0f, p1 = 0.0f, p2 = 0.0f;
    for (int d = tid; d < Dn; d += 256) {
        float tm = g_tmax[(size_t)b * Dn + d];
        float gt = 0.0f;
        for (int n = gs; n < ge; ++n)
            gt += g_x[((size_t)b * Nn + n) * Dn + d];
        p0 += tm * fcW[d * On + 0] + gt * fcW[(Dn + d) * On + 0];
        p1 += tm * fcW[d * On + 1] + gt * fcW[(Dn + d) * On + 1];
        p2 += tm * fcW[d * On + 2] + gt * fcW[(Dn + d) * On + 2];
    }
    __shared__ float r0[256], r1[256], r2[256];
    r0[tid] = p0; r1[tid] = p1; r2[tid] = p2;
    __syncthreads();
    #pragma unroll
    for (int st = 128; st > 0; st >>= 1) {
        if (tid < st) { r0[tid] += r0[tid + st]; r1[tid] += r1[tid + st]; r2[tid] += r2[tid + st]; }
        __syncthreads();
    }
    if (tid == 0) {
        out[b * On + 0] = tanhf(r0[0] + fcb[0]);
        out[b * On + 1] = tanhf(r1[0] + fcb[1]);
        out[b * On + 2] = tanhf(r2[0] + fcb[2]);
    }
}

// ---------------------------------------------------------------------------
extern "C" void kernel_launch(void* const* d_in, const int* in_sizes, int n_in,
                              void* d_out, int out_size) {
    const float* se     = (const float*)d_in[0];   // [B,S,D]
    const float* dg     = (const float*)d_in[1];   // [B,N,N]
    const float* dg1    = (const float*)d_in[2];   // [B,N,N]
    const float* Wproj  = (const float*)d_in[3];   // [D,D]
    const float* Wg1    = (const float*)d_in[4];
    const float* bg1    = (const float*)d_in[5];
    const float* Wg2    = (const float*)d_in[6];
    const float* bg2    = (const float*)d_in[7];
    const float* Wg3    = (const float*)d_in[8];
    const float* bg3    = (const float*)d_in[9];
    const float* fcW    = (const float*)d_in[10];  // [2D,O]
    const float* fcb    = (const float*)d_in[11];  // [O]
    const int*   tspan  = (const int*)d_in[12];    // [B,2]
    const int*   tran   = (const int*)d_in[13];    // [B,N,2]
    const int*   gspan  = (const int*)d_in[14];    // [B,2]
    float* out = (float*)d_out;

    float *px, *pt;
    cudaGetSymbolAddress((void**)&px, g_x);
    cudaGetSymbolAddress((void**)&pt, g_t);

    const int M = Bn * Nn;                 // 8192
    dim3 gemm_grid(Dn / 128, M / 128);     // (6, 64)

    adj_kernel<<<Bn * Nn, 128>>>(dg, dg1);
    span_kernel<<<Bn * Nn, 256>>>(se, tran);          // tmps -> g_t
    tmax_kernel<<<Bn, 256>>>(se, tspan);

    // x = relu(tmps @ W_proj)
    sgemm_kernel<true><<<gemm_grid, 256>>>(pt, Wproj, px, M, Dn, Dn);

    // 3 GCN layers
    sgemm_kernel<false><<<gemm_grid, 256>>>(px, Wg1, pt, M, Dn, Dn);
    adj_spmm_kernel<<<Bn * Nn, 256>>>(bg1);
    sgemm_kernel<false><<<gemm_grid, 256>>>(px, Wg2, pt, M, Dn, Dn);
    adj_spmm_kernel<<<Bn * Nn, 256>>>(bg2);
    sgemm_kernel<false><<<gemm_grid, 256>>>(px, Wg3, pt, M, Dn, Dn);
    adj_spmm_kernel<<<Bn * Nn, 256>>>(bg3);

    head_kernel<<<Bn, 256>>>(fcW, fcb, gspan, out);
}

// round 3
// speedup vs baseline: 1.6025x; 1.6025x over previous
#include <cuda_runtime.h>
#include <cstdint>

// Problem constants
#define Bn 64
#define Sn 512
#define Nn 128
#define Dn 768
#define On 3

// Scratch (device globals -- no allocations allowed)
__device__ float g_x[(size_t)Bn * Nn * Dn];      // node features (residual stream)
__device__ float g_t[(size_t)Bn * Nn * Dn];      // tmps (span sums), row-major [B*N, D]
__device__ float g_tT[(size_t)Bn * Dn * Nn];     // (x@W)^T per batch: [B][D][N]
__device__ float g_adj[(size_t)Bn * Nn * Nn];    // clamped adjacency
__device__ float g_denom[(size_t)Bn * Nn];       // row-degree + 1e-7
__device__ float g_tmax[(size_t)Bn * Dn];        // target max-pool
__device__ float g_Wt[4 * (size_t)Dn * Dn];      // transposed weights [N,K] K-major

// ===========================================================================
// helpers
// ===========================================================================
__device__ __forceinline__ uint32_t smem_u32(const void* p) {
    uint32_t a;
    asm("{ .reg .u64 t; cvta.to.shared.u64 t, %1; cvt.u32.u64 %0, t; }" : "=r"(a) : "l"(p));
    return a;
}
__device__ __forceinline__ uint32_t f2tf32(float f) {
    uint32_t u;
    asm("cvt.rna.tf32.f32 %0, %1;" : "=r"(u) : "f"(f));
    return u;
}
#define CP_ASYNC16(dst, src) \
    asm volatile("cp.async.cg.shared.global [%0], [%1], 16;" :: "r"(dst), "l"(src) : "memory")
#define CP_COMMIT() asm volatile("cp.async.commit_group;" ::: "memory")
#define CP_WAIT(n)  asm volatile("cp.async.wait_group %0;" :: "n"(n) : "memory")

__device__ __forceinline__ void mma_tf32(float& c0, float& c1, float& c2, float& c3,
                                         uint32_t a0, uint32_t a1, uint32_t a2, uint32_t a3,
                                         uint32_t b0, uint32_t b1) {
    asm volatile(
        "mma.sync.aligned.m16n8k8.row.col.f32.tf32.tf32.f32 "
        "{%0,%1,%2,%3}, {%4,%5,%6,%7}, {%8,%9}, {%0,%1,%2,%3};"
        : "+f"(c0), "+f"(c1), "+f"(c2), "+f"(c3)
        : "r"(a0), "r"(a1), "r"(a2), "r"(a3), "r"(b0), "r"(b1));
}

// ===========================================================================
// small prep kernels
// ===========================================================================
__global__ void adj_kernel(const float* __restrict__ dg, const float* __restrict__ dg1) {
    int row = blockIdx.x;
    int tid = threadIdx.x;
    float a = dg[(size_t)row * Nn + tid] + dg1[(size_t)row * Nn + tid];
    a = fminf(a, 1.0f);
    g_adj[(size_t)row * Nn + tid] = a;
    __shared__ float s[128];
    s[tid] = a;
    __syncthreads();
    #pragma unroll
    for (int st = 64; st > 0; st >>= 1) {
        if (tid < st) s[tid] += s[tid + st];
        __syncthreads();
    }
    if (tid == 0) g_denom[row] = s[0] + 1e-7f;
}

__global__ void span_kernel(const float* __restrict__ se, const int* __restrict__ tran) {
    int row = blockIdx.x;
    int b = row >> 7;
    int s0 = tran[row * 2] + 1;
    int e0 = tran[row * 2 + 1] + 1;
    for (int d = threadIdx.x; d < Dn; d += 256) {
        float acc = 0.0f;
        for (int s = s0; s < e0; ++s)
            acc += se[((size_t)b * Sn + s) * Dn + d];
        g_t[(size_t)row * Dn + d] = acc;
    }
}

__global__ void tmax_kernel(const float* __restrict__ se, const int* __restrict__ tspan) {
    int b = blockIdx.x;
    int l = tspan[b * 2];
    int r = tspan[b * 2 + 1];
    for (int d = threadIdx.x; d < Dn; d += 256) {
        float m = -3.402823466e38f;
        for (int s = l; s < r; ++s)
            m = fmaxf(m, se[((size_t)b * Sn + s) * Dn + d]);
        g_tmax[(size_t)b * Dn + d] = m;
    }
}

// transpose 4 weight matrices [K=768, N=768] -> g_Wt[w][N][K]
__global__ void wtrans_kernel(const float* __restrict__ W0, const float* __restrict__ W1,
                              const float* __restrict__ W2, const float* __restrict__ W3) {
    __shared__ float t[32][33];
    int w = blockIdx.z;
    const float* W = (w == 0) ? W0 : (w == 1) ? W1 : (w == 2) ? W2 : W3;
    float* O = g_Wt + (size_t)w * Dn * Dn;
    int nx = blockIdx.x * 32;
    int ky = blockIdx.y * 32;
    int tx = threadIdx.x;
    for (int i = threadIdx.y; i < 32; i += 8)
        t[i][tx] = W[(size_t)(ky + i) * Dn + nx + tx];
    __syncthreads();
    for (int i = threadIdx.y; i < 32; i += 8)
        O[(size_t)(nx + i) * Dn + ky + tx] = t[tx][i];
}

// ===========================================================================
// tf32 mma.sync GEMM: C[M,N] = A[M,K] @ B^T  (B given as [N,K] K-major)
// 128x128 block tile, BK=16, 256 threads (8 warps of 64x32), 2-stage cp.async
// MODE 0: C = relu(acc), row-major             (proj: g_t @ Wt -> g_x)
// MODE 1: C^T per-batch store into g_tT        (h@W)
// MODE 2: g_x += relu(acc/denom + bias)        (adjacency layer)
// ===========================================================================
#define BK 16
#define TSTRIDE 20                    // padded row stride in floats
#define TILE_F (128 * TSTRIDE)        // 2560 floats per tile

template <int MODE, int KTILES>
__global__ void __launch_bounds__(256, 1)
gemm_mma(const float* __restrict__ A, const float* __restrict__ B, float* __restrict__ C,
         const float* __restrict__ bias, int lda, int ldb) {
    __shared__ float smem[4 * TILE_F];   // [buf][A|B] ; reused by MODE1 epilogue
    float* As[2] = { smem,            smem + 2 * TILE_F };
    float* Bs[2] = { smem + TILE_F,   smem + 3 * TILE_F };

    int tid = threadIdx.x;
    int lane = tid & 31;
    int warp = tid >> 5;
    int wm = (warp >> 2) * 64;    // warp row base (0/64)
    int wn = (warp & 3) * 32;     // warp col base (0..96)
    int lg = lane >> 2;           // group id 0..7
    int tg = lane & 3;            // thread-in-group 0..3

    const float* Ab;
    const float* Bb;
    int aRow0, bRow0;
    if (MODE == 2) {
        Ab = A + (size_t)blockIdx.y * Nn * Nn;     // adj[b]
        Bb = B + (size_t)blockIdx.y * Dn * Nn;     // g_tT[b]
        aRow0 = 0;
        bRow0 = blockIdx.x * 128;
    } else {
        Ab = A;
        Bb = B;
        aRow0 = blockIdx.y * 128;
        bRow0 = blockIdx.x * 128;
    }

    float c[4][4][4];
    #pragma unroll
    for (int i = 0; i < 4; ++i)
        #pragma unroll
        for (int j = 0; j < 4; ++j)
            #pragma unroll
            for (int k = 0; k < 4; ++k) c[i][j][k] = 0.0f;

    uint32_t sAbase[2], sBbase[2];
    #pragma unroll
    for (int s = 0; s < 2; ++s) {
        sAbase[s] = smem_u32(As[s]);
        sBbase[s] = smem_u32(Bs[s]);
    }

    // loader: 512 16B chunks per tile pair; thread does 2 A + 2 B chunks
    auto load_stage = [&](int it, int buf) {
        int k0 = it * BK;
        #pragma unroll
        for (int i = 0; i < 2; ++i) {
            int id = tid + i * 256;      // 0..511
            int row = id >> 2;
            int seg = id & 3;
            CP_ASYNC16(sAbase[buf] + (row * TSTRIDE + seg * 4) * 4,
                       Ab + (size_t)(aRow0 + row) * lda + k0 + seg * 4);
            CP_ASYNC16(sBbase[buf] + (row * TSTRIDE + seg * 4) * 4,
                       Bb + (size_t)(bRow0 + row) * ldb + k0 + seg * 4);
        }
        CP_COMMIT();
    };

    load_stage(0, 0);
    for (int it = 0; it < KTILES; ++it) {
        int buf = it & 1;
        if (it + 1 < KTILES) {
            load_stage(it + 1, buf ^ 1);
            CP_WAIT(1);
        } else {
            CP_WAIT(0);
        }
        __syncthreads();
        const float* as = As[buf];
        const float* bs = Bs[buf];
        #pragma unroll
        for (int ks = 0; ks < 2; ++ks) {
            int k0 = ks * 8;
            uint32_t af[4][4], bf[4][2];
            #pragma unroll
            for (int mi = 0; mi < 4; ++mi) {
                int r = wm + mi * 16 + lg;
                af[mi][0] = f2tf32(as[r * TSTRIDE + k0 + tg]);
                af[mi][1] = f2tf32(as[(r + 8) * TSTRIDE + k0 + tg]);
                af[mi][2] = f2tf32(as[r * TSTRIDE + k0 + tg + 4]);
                af[mi][3] = f2tf32(as[(r + 8) * TSTRIDE + k0 + tg + 4]);
            }
            #pragma unroll
            for (int ni = 0; ni < 4; ++ni) {
                int n = wn + ni * 8 + lg;
                bf[ni][0] = f2tf32(bs[n * TSTRIDE + k0 + tg]);
                bf[ni][1] = f2tf32(bs[n * TSTRIDE + k0 + tg + 4]);
            }
            #pragma unroll
            for (int mi = 0; mi < 4; ++mi)
                #pragma unroll
                for (int ni = 0; ni < 4; ++ni)
                    mma_tf32(c[mi][ni][0], c[mi][ni][1], c[mi][ni][2], c[mi][ni][3],
                             af[mi][0], af[mi][1], af[mi][2], af[mi][3],
                             bf[ni][0], bf[ni][1]);
        }
        __syncthreads();
    }

    // ---- epilogue ----
    if (MODE == 0) {
        float* cp = C + (size_t)(blockIdx.y * 128) * Dn + blockIdx.x * 128;
        #pragma unroll
        for (int mi = 0; mi < 4; ++mi) {
            int r = wm + mi * 16 + lg;
            #pragma unroll
            for (int ni = 0; ni < 4; ++ni) {
                int cc = wn + ni * 8 + 2 * tg;
                cp[(size_t)r * Dn + cc]           = fmaxf(c[mi][ni][0], 0.0f);
                cp[(size_t)r * Dn + cc + 1]       = fmaxf(c[mi][ni][1], 0.0f);
                cp[(size_t)(r + 8) * Dn + cc]     = fmaxf(c[mi][ni][2], 0.0f);
                cp[(size_t)(r + 8) * Dn + cc + 1] = fmaxf(c[mi][ni][3], 0.0f);
            }
        }
    } else if (MODE == 1) {
        // stage C^T through smem, 64 columns at a time; store coalesced tT rows
        int b = blockIdx.y;
        float* outb = C + ((size_t)b * Dn + blockIdx.x * 128) * Nn;
        #pragma unroll
        for (int half = 0; half < 2; ++half) {
            __syncthreads();
            // warps with wn in this half deposit their fragments: sc[c_local][r]
            if ((wn >> 6) == half) {
                #pragma unroll
                for (int mi = 0; mi < 4; ++mi) {
                    int r = wm + mi * 16 + lg;
                    #pragma unroll
                    for (int ni = 0; ni < 4; ++ni) {
                        int cl = (wn & 63) + ni * 8 + 2 * tg;
                        smem[cl * 132 + r]           = c[mi][ni][0];
                        smem[cl * 132 + r + 1 * 0 + 0 + 0] = c[mi][ni][0];
                        smem[cl * 132 + r]           = c[mi][ni][0];
                        smem[(cl + 1) * 132 + r]     = c[mi][ni][1];
                        smem[cl * 132 + r + 8]       = c[mi][ni][2];
                        smem[(cl + 1) * 132 + r + 8] = c[mi][ni][3];
                    }
                }
            }
            __syncthreads();
            // write 64 tT rows (each 128 floats) coalesced
            for (int i = tid; i < 64 * 32; i += 256) {
                int row = i >> 5;         // local d
                int seg = i & 31;         // float4 index
                float4 v;
                v.x = smem[row * 132 + seg * 4 + 0];
                v.y = smem[row * 132 + seg * 4 + 1];
                v.z = smem[row * 132 + seg * 4 + 2];
                v.w = smem[row * 132 + seg * 4 + 3];
                *(float4*)&outb[(size_t)(half * 64 + row) * Nn + seg * 4] = v;
            }
        }
    } else {
        int b = blockIdx.y;
        const float* bp = bias + blockIdx.x * 128;
        #pragma unroll
        for (int mi = 0; mi < 4; ++mi) {
            int r = wm + mi * 16 + lg;
            float id0 = 1.0f / g_denom[b * Nn + r];
            float id1 = 1.0f / g_denom[b * Nn + r + 8];
            float* x0 = g_x + (size_t)(b * Nn + r) * Dn + blockIdx.x * 128;
            float* x1 = g_x + (size_t)(b * Nn + r + 8) * Dn + blockIdx.x * 128;
            #pragma unroll
            for (int ni = 0; ni < 4; ++ni) {
                int cc = wn + ni * 8 + 2 * tg;
                x0[cc]     += fmaxf(c[mi][ni][0] * id0 + bp[cc], 0.0f);
                x0[cc + 1] += fmaxf(c[mi][ni][1] * id0 + bp[cc + 1], 0.0f);
                x1[cc]     += fmaxf(c[mi][ni][2] * id1 + bp[cc], 0.0f);
                x1[cc + 1] += fmaxf(c[mi][ni][3] * id1 + bp[cc + 1], 0.0f);
            }
        }
    }
}

// ===========================================================================
// head: gcn_target (node-span sum) + concat + fc + tanh
// ===========================================================================
__global__ void head_kernel(const float* __restrict__ fcW, const float* __restrict__ fcb,
                            const int* __restrict__ gspan, float* __restrict__ out) {
    int b = blockIdx.x;
    int tid = threadIdx.x;
    int gs = gspan[b * 2];
    int ge = gspan[b * 2 + 1];
    float p0 = 0.0f, p1 = 0.0f, p2 = 0.0f;
    for (int d = tid; d < Dn; d += 256) {
        float tm = g_tmax[(size_t)b * Dn + d];
        float gt = 0.0f;
        for (int n = gs; n < ge; ++n)
            gt += g_x[((size_t)b * Nn + n) * Dn + d];
        p0 += tm * fcW[d * On + 0] + gt * fcW[(Dn + d) * On + 0];
        p1 += tm * fcW[d * On + 1] + gt * fcW[(Dn + d) * On + 1];
        p2 += tm * fcW[d * On + 2] + gt * fcW[(Dn + d) * On + 2];
    }
    __shared__ float r0[256], r1[256], r2[256];
    r0[tid] = p0; r1[tid] = p1; r2[tid] = p2;
    __syncthreads();
    #pragma unroll
    for (int st = 128; st > 0; st >>= 1) {
        if (tid < st) { r0[tid] += r0[tid + st]; r1[tid] += r1[tid + st]; r2[tid] += r2[tid + st]; }
        __syncthreads();
    }
    if (tid == 0) {
        out[b * On + 0] = tanhf(r0[0] + fcb[0]);
        out[b * On + 1] = tanhf(r1[0] + fcb[1]);
        out[b * On + 2] = tanhf(r2[0] + fcb[2]);
    }
}

// ===========================================================================
extern "C" void kernel_launch(void* const* d_in, const int* in_sizes, int n_in,
                              void* d_out, int out_size) {
    const float* se    = (const float*)d_in[0];
    const float* dg    = (const float*)d_in[1];
    const float* dg1   = (const float*)d_in[2];
    const float* Wproj = (const float*)d_in[3];
    const float* Wg1   = (const float*)d_in[4];
    const float* bg1   = (const float*)d_in[5];
    const float* Wg2   = (const float*)d_in[6];
    const float* bg2   = (const float*)d_in[7];
    const float* Wg3   = (const float*)d_in[8];
    const float* bg3   = (const float*)d_in[9];
    const float* fcW   = (const float*)d_in[10];
    const float* fcb   = (const float*)d_in[11];
    const int*   tspan = (const int*)d_in[12];
    const int*   tran  = (const int*)d_in[13];
    const int*   gspan = (const int*)d_in[14];
    float* out = (float*)d_out;

    float *px, *pt, *ptT, *padj, *pWt;
    cudaGetSymbolAddress((void**)&px, g_x);
    cudaGetSymbolAddress((void**)&pt, g_t);
    cudaGetSymbolAddress((void**)&ptT, g_tT);
    cudaGetSymbolAddress((void**)&padj, g_adj);
    cudaGetSymbolAddress((void**)&pWt, g_Wt);

    dim3 gg(6, 64);

    adj_kernel<<<Bn * Nn, 128>>>(dg, dg1);
    span_kernel<<<Bn * Nn, 256>>>(se, tran);
    tmax_kernel<<<Bn, 256>>>(se, tspan);
    wtrans_kernel<<<dim3(24, 24, 4), dim3(32, 8)>>>(Wproj, Wg1, Wg2, Wg3);

    const size_t WSZ = (size_t)Dn * Dn;

    // x = relu(tmps @ W_proj)
    gemm_mma<0, 48><<<gg, 256>>>(pt, pWt + 0 * WSZ, px, nullptr, Dn, Dn);

    // 3 GCN layers: tT = (x @ Wg)^T ; x += relu(adj @ t / denom + b)
    gemm_mma<1, 48><<<gg, 256>>>(px, pWt + 1 * WSZ, ptT, nullptr, Dn, Dn);
    gemm_mma<2, 8><<<gg, 256>>>(padj, ptT, px, bg1, Nn, Nn);
    gemm_mma<1, 48><<<gg, 256>>>(px, pWt + 2 * WSZ, ptT, nullptr, Dn, Dn);
    gemm_mma<2, 8><<<gg, 256>>>(padj, ptT, px, bg2, Nn, Nn);
    gemm_mma<1, 48><<<gg, 256>>>(px, pWt + 3 * WSZ, ptT, nullptr, Dn, Dn);
    gemm_mma<2, 8><<<gg, 256>>>(padj, ptT, px, bg3, Nn, Nn);

    head_kernel<<<Bn, 256>>>(fcW, fcb, gspan, out);
}

// round 4
// speedup vs baseline: 1.6659x; 1.0395x over previous
#include <cuda_runtime.h>
#include <cstdint>

// Problem constants
#define Bn 64
#define Sn 512
#define Nn 128
#define Dn 768
#define On 3

// Scratch (device globals -- no allocations allowed)
__device__ float g_x[(size_t)Bn * Nn * Dn];      // exact node features (residual stream)
__device__ float g_xr[(size_t)Bn * Nn * Dn];     // tf32-rounded, K-permuted copy (MMA input)
__device__ float g_t[(size_t)Bn * Nn * Dn];      // span sums, rounded+permuted [B*N, D]
__device__ float g_tT[(size_t)Bn * Dn * Nn];     // (x@W)^T per batch, rounded+permuted [B][D][N]
__device__ float g_adj[(size_t)Bn * Nn * Nn];    // clamped adjacency, permuted cols (exact 0/1)
__device__ float g_denom[(size_t)Bn * Nn];       // row-degree + 1e-7
__device__ float g_tmax[(size_t)Bn * Dn];        // target max-pool
__device__ float g_Wt[4 * (size_t)Dn * Dn];      // W^T [N,K], rounded + K-permuted

// ===========================================================================
// helpers
// ===========================================================================
__device__ __forceinline__ uint32_t smem_u32(const void* p) {
    uint32_t a;
    asm("{ .reg .u64 t; cvta.to.shared.u64 t, %1; cvt.u32.u64 %0, t; }" : "=r"(a) : "l"(p));
    return a;
}
__device__ __forceinline__ float f2tf(float f) {
    uint32_t u;
    asm("cvt.rna.tf32.f32 %0, %1;" : "=r"(u) : "f"(f));
    return __uint_as_float(u);
}
// K-permutation within each 16-column group (involution)
__device__ __forceinline__ int permc(int c) {
    return (c & ~15) | ((c & 3) << 2) | ((c >> 2) & 3);
}
#define CP_ASYNC16(dst, src) \
    asm volatile("cp.async.cg.shared.global [%0], [%1], 16;" :: "r"(dst), "l"(src) : "memory")
#define CP_COMMIT() asm volatile("cp.async.commit_group;" ::: "memory")
#define CP_WAIT(n)  asm volatile("cp.async.wait_group %0;" :: "n"(n) : "memory")

__device__ __forceinline__ void mma_tf32(float& c0, float& c1, float& c2, float& c3,
                                         float a0, float a1, float a2, float a3,
                                         float b0, float b1) {
    asm volatile(
        "mma.sync.aligned.m16n8k8.row.col.f32.tf32.tf32.f32 "
        "{%0,%1,%2,%3}, {%4,%5,%6,%7}, {%8,%9}, {%0,%1,%2,%3};"
        : "+f"(c0), "+f"(c1), "+f"(c2), "+f"(c3)
        : "r"(__float_as_uint(a0)), "r"(__float_as_uint(a1)),
          "r"(__float_as_uint(a2)), "r"(__float_as_uint(a3)),
          "r"(__float_as_uint(b0)), "r"(__float_as_uint(b1)));
}

// ===========================================================================
// small prep kernels
// ===========================================================================
__global__ void adj_kernel(const float* __restrict__ dg, const float* __restrict__ dg1) {
    int row = blockIdx.x;
    int tid = threadIdx.x;
    float a = dg[(size_t)row * Nn + tid] + dg1[(size_t)row * Nn + tid];
    a = fminf(a, 1.0f);
    g_adj[(size_t)row * Nn + permc(tid)] = a;    // exact 0/1, permuted K(=node) cols
    __shared__ float s[128];
    s[tid] = a;
    __syncthreads();
    #pragma unroll
    for (int st = 64; st > 0; st >>= 1) {
        if (tid < st) s[tid] += s[tid + st];
        __syncthreads();
    }
    if (tid == 0) g_denom[row] = s[0] + 1e-7f;
}

__global__ void span_kernel(const float* __restrict__ se, const int* __restrict__ tran) {
    int row = blockIdx.x;
    int b = row >> 7;
    int s0 = tran[row * 2] + 1;
    int e0 = tran[row * 2 + 1] + 1;
    for (int d = threadIdx.x; d < Dn; d += 256) {
        float acc = 0.0f;
        for (int s = s0; s < e0; ++s)
            acc += se[((size_t)b * Sn + s) * Dn + d];
        g_t[(size_t)row * Dn + permc(d)] = f2tf(acc);
    }
}

__global__ void tmax_kernel(const float* __restrict__ se, const int* __restrict__ tspan) {
    int b = blockIdx.x;
    int l = tspan[b * 2];
    int r = tspan[b * 2 + 1];
    for (int d = threadIdx.x; d < Dn; d += 256) {
        float m = -3.402823466e38f;
        for (int s = l; s < r; ++s)
            m = fmaxf(m, se[((size_t)b * Sn + s) * Dn + d]);
        g_tmax[(size_t)b * Dn + d] = m;
    }
}

// transpose + round + K-permute 4 weight matrices [K=768, N=768] -> g_Wt[w][N][Kperm]
__global__ void wtrans_kernel(const float* __restrict__ W0, const float* __restrict__ W1,
                              const float* __restrict__ W2, const float* __restrict__ W3) {
    __shared__ float t[32][33];
    int w = blockIdx.z;
    const float* W = (w == 0) ? W0 : (w == 1) ? W1 : (w == 2) ? W2 : W3;
    float* O = g_Wt + (size_t)w * Dn * Dn;
    int nx = blockIdx.x * 32;
    int ky = blockIdx.y * 32;
    int tx = threadIdx.x;
    for (int i = threadIdx.y; i < 32; i += 8)
        t[i][tx] = W[(size_t)(ky + i) * Dn + nx + tx];
    __syncthreads();
    for (int i = threadIdx.y; i < 32; i += 8)
        O[(size_t)(nx + i) * Dn + permc(ky + tx)] = f2tf(t[tx][i]);
}

// ===========================================================================
// tf32 mma.sync GEMM: C[M,N] = A[M,K] @ B^T  (B as [N,K]; K pre-permuted, tf32)
// 128x128 block tile, BK=16, 256 threads (8 warps of 64x32), 2-stage cp.async
// MODE 0: g_x = relu(acc) (exact) + g_xr rounded/permuted    (proj)
// MODE 1: C^T per-batch store into g_tT (rounded/permuted)   (h@W)
// MODE 2: g_x += relu(acc/denom + bias); g_xr rounded copy   (adjacency)
// ===========================================================================
#define BK 16
#define TSTRIDE 20
#define TILE_F (128 * TSTRIDE)

template <int MODE, int KTILES>
__global__ void __launch_bounds__(256, 1)
gemm_mma(const float* __restrict__ A, const float* __restrict__ B,
         const float* __restrict__ bias, int lda, int ldb) {
    __shared__ float smem[4 * TILE_F];
    float* As[2] = { smem,          smem + 2 * TILE_F };
    float* Bs[2] = { smem + TILE_F, smem + 3 * TILE_F };

    int tid = threadIdx.x;
    int lane = tid & 31;
    int warp = tid >> 5;
    int wm = (warp >> 2) * 64;    // warp row base (0/64)
    int wn = (warp & 3) * 32;     // warp col base (0..96)
    int lg = lane >> 2;           // 0..7
    int tg = lane & 3;            // 0..3

    const float* Ab;
    const float* Bb;
    int aRow0, bRow0;
    if (MODE == 2) {
        Ab = A + (size_t)blockIdx.y * Nn * Nn;     // adj[b]
        Bb = B + (size_t)blockIdx.y * Dn * Nn;     // g_tT[b]
        aRow0 = 0;
        bRow0 = blockIdx.x * 128;
    } else {
        Ab = A;
        Bb = B;
        aRow0 = blockIdx.y * 128;
        bRow0 = blockIdx.x * 128;
    }

    float c[4][4][4];
    #pragma unroll
    for (int i = 0; i < 4; ++i)
        #pragma unroll
        for (int j = 0; j < 4; ++j)
            #pragma unroll
            for (int k = 0; k < 4; ++k) c[i][j][k] = 0.0f;

    uint32_t sAbase[2], sBbase[2];
    #pragma unroll
    for (int s = 0; s < 2; ++s) {
        sAbase[s] = smem_u32(As[s]);
        sBbase[s] = smem_u32(Bs[s]);
    }

    auto load_stage = [&](int it, int buf) {
        int k0 = it * BK;
        #pragma unroll
        for (int i = 0; i < 2; ++i) {
            int id = tid + i * 256;
            int row = id >> 2;
            int seg = id & 3;
            CP_ASYNC16(sAbase[buf] + (row * TSTRIDE + seg * 4) * 4,
                       Ab + (size_t)(aRow0 + row) * lda + k0 + seg * 4);
            CP_ASYNC16(sBbase[buf] + (row * TSTRIDE + seg * 4) * 4,
                       Bb + (size_t)(bRow0 + row) * ldb + k0 + seg * 4);
        }
        CP_COMMIT();
    };

    load_stage(0, 0);
    for (int it = 0; it < KTILES; ++it) {
        int buf = it & 1;
        if (it + 1 < KTILES) {
            load_stage(it + 1, buf ^ 1);
            CP_WAIT(1);
        } else {
            CP_WAIT(0);
        }
        __syncthreads();
        const float* as = As[buf];
        const float* bs = Bs[buf];
        // physical cols [4tg..4tg+3] hold logical k = {tg, tg+4, tg+8, tg+12}
        float4 av[4][2], bv[4];
        #pragma unroll
        for (int mi = 0; mi < 4; ++mi) {
            av[mi][0] = *(const float4*)&as[(wm + mi * 16 + lg) * TSTRIDE + 4 * tg];
            av[mi][1] = *(const float4*)&as[(wm + mi * 16 + lg + 8) * TSTRIDE + 4 * tg];
        }
        #pragma unroll
        for (int ni = 0; ni < 4; ++ni)
            bv[ni] = *(const float4*)&bs[(wn + ni * 8 + lg) * TSTRIDE + 4 * tg];
        #pragma unroll
        for (int mi = 0; mi < 4; ++mi)
            #pragma unroll
            for (int ni = 0; ni < 4; ++ni) {
                mma_tf32(c[mi][ni][0], c[mi][ni][1], c[mi][ni][2], c[mi][ni][3],
                         av[mi][0].x, av[mi][1].x, av[mi][0].y, av[mi][1].y,
                         bv[ni].x, bv[ni].y);
                mma_tf32(c[mi][ni][0], c[mi][ni][1], c[mi][ni][2], c[mi][ni][3],
                         av[mi][0].z, av[mi][1].z, av[mi][0].w, av[mi][1].w,
                         bv[ni].z, bv[ni].w);
            }
        __syncthreads();
    }

    // ---- epilogue ----
    if (MODE == 0) {
        size_t row0 = (size_t)blockIdx.y * 128;
        #pragma unroll
        for (int mi = 0; mi < 4; ++mi) {
            int r = wm + mi * 16 + lg;
            #pragma unroll
            for (int ni = 0; ni < 4; ++ni) {
                int cc = blockIdx.x * 128 + wn + ni * 8 + 2 * tg;
                float v0 = fmaxf(c[mi][ni][0], 0.0f);
                float v1 = fmaxf(c[mi][ni][1], 0.0f);
                float v2 = fmaxf(c[mi][ni][2], 0.0f);
                float v3 = fmaxf(c[mi][ni][3], 0.0f);
                g_x[(row0 + r) * Dn + cc]          = v0;
                g_x[(row0 + r) * Dn + cc + 1]      = v1;
                g_x[(row0 + r + 8) * Dn + cc]      = v2;
                g_x[(row0 + r + 8) * Dn + cc + 1]  = v3;
                g_xr[(row0 + r) * Dn + permc(cc)]         = f2tf(v0);
                g_xr[(row0 + r) * Dn + permc(cc + 1)]     = f2tf(v1);
                g_xr[(row0 + r + 8) * Dn + permc(cc)]     = f2tf(v2);
                g_xr[(row0 + r + 8) * Dn + permc(cc + 1)] = f2tf(v3);
            }
        }
    } else if (MODE == 1) {
        int b = blockIdx.y;
        float* outb = g_tT + ((size_t)b * Dn + blockIdx.x * 128) * Nn;
        #pragma unroll
        for (int half = 0; half < 2; ++half) {
            __syncthreads();
            if ((wn >> 6) == half) {
                #pragma unroll
                for (int mi = 0; mi < 4; ++mi) {
                    int r = wm + mi * 16 + lg;
                    #pragma unroll
                    for (int ni = 0; ni < 4; ++ni) {
                        int cl = (wn & 63) + ni * 8 + 2 * tg;
                        smem[cl * 132 + r]           = c[mi][ni][0];
                        smem[(cl + 1) * 132 + r]     = c[mi][ni][1];
                        smem[cl * 132 + r + 8]       = c[mi][ni][2];
                        smem[(cl + 1) * 132 + r + 8] = c[mi][ni][3];
                    }
                }
            }
            __syncthreads();
            // write 64 tT rows (each 128 floats) coalesced; permute K(=node) cols
            for (int i = tid; i < 64 * 32; i += 256) {
                int row = i >> 5;
                int seg = i & 31;
                float4 v;
                v.x = f2tf(smem[row * 132 + permc(seg * 4 + 0)]);
                v.y = f2tf(smem[row * 132 + permc(seg * 4 + 1)]);
                v.z = f2tf(smem[row * 132 + permc(seg * 4 + 2)]);
                v.w = f2tf(smem[row * 132 + permc(seg * 4 + 3)]);
                *(float4*)&outb[(size_t)(half * 64 + row) * Nn + seg * 4] = v;
            }
        }
    } else {
        int b = blockIdx.y;
        #pragma unroll
        for (int mi = 0; mi < 4; ++mi) {
            int r = wm + mi * 16 + lg;
            float id0 = 1.0f / g_denom[b * Nn + r];
            float id1 = 1.0f / g_denom[b * Nn + r + 8];
            size_t row0 = (size_t)(b * Nn + r);
            size_t row1 = row0 + 8;
            #pragma unroll
            for (int ni = 0; ni < 4; ++ni) {
                int cc = blockIdx.x * 128 + wn + ni * 8 + 2 * tg;
                float n0 = g_x[row0 * Dn + cc]     + fmaxf(c[mi][ni][0] * id0 + bias[cc], 0.0f);
                float n1 = g_x[row0 * Dn + cc + 1] + fmaxf(c[mi][ni][1] * id0 + bias[cc + 1], 0.0f);
                float n2 = g_x[row1 * Dn + cc]     + fmaxf(c[mi][ni][2] * id1 + bias[cc], 0.0f);
                float n3 = g_x[row1 * Dn + cc + 1] + fmaxf(c[mi][ni][3] * id1 + bias[cc + 1], 0.0f);
                g_x[row0 * Dn + cc]     = n0;
                g_x[row0 * Dn + cc + 1] = n1;
                g_x[row1 * Dn + cc]     = n2;
                g_x[row1 * Dn + cc + 1] = n3;
                g_xr[row0 * Dn + permc(cc)]     = f2tf(n0);
                g_xr[row0 * Dn + permc(cc + 1)] = f2tf(n1);
                g_xr[row1 * Dn + permc(cc)]     = f2tf(n2);
                g_xr[row1 * Dn + permc(cc + 1)] = f2tf(n3);
            }
        }
    }
}

// ===========================================================================
// head: gcn_target (node-span sum) + concat + fc + tanh
// ===========================================================================
__global__ void head_kernel(const float* __restrict__ fcW, const float* __restrict__ fcb,
                            const int* __restrict__ gspan, float* __restrict__ out) {
    int b = blockIdx.x;
    int tid = threadIdx.x;
    int gs = gspan[b * 2];
    int ge = gspan[b * 2 + 1];
    float p0 = 0.0f, p1 = 0.0f, p2 = 0.0f;
    for (int d = tid; d < Dn; d += 256) {
        float tm = g_tmax[(size_t)b * Dn + d];
        float gt = 0.0f;
        for (int n = gs; n < ge; ++n)
            gt += g_x[((size_t)b * Nn + n) * Dn + d];
        p0 += tm * fcW[d * On + 0] + gt * fcW[(Dn + d) * On + 0];
        p1 += tm * fcW[d * On + 1] + gt * fcW[(Dn + d) * On + 1];
        p2 += tm * fcW[d * On + 2] + gt * fcW[(Dn + d) * On + 2];
    }
    __shared__ float r0[256], r1[256], r2[256];
    r0[tid] = p0; r1[tid] = p1; r2[tid] = p2;
    __syncthreads();
    #pragma unroll
    for (int st = 128; st > 0; st >>= 1) {
        if (tid < st) { r0[tid] += r0[tid + st]; r1[tid] += r1[tid + st]; r2[tid] += r2[tid + st]; }
        __syncthreads();
    }
    if (tid == 0) {
        out[b * On + 0] = tanhf(r0[0] + fcb[0]);
        out[b * On + 1] = tanhf(r1[0] + fcb[1]);
        out[b * On + 2] = tanhf(r2[0] + fcb[2]);
    }
}

// ===========================================================================
extern "C" void kernel_launch(void* const* d_in, const int* in_sizes, int n_in,
                              void* d_out, int out_size) {
    const float* se    = (const float*)d_in[0];
    const float* dg    = (const float*)d_in[1];
    const float* dg1   = (const float*)d_in[2];
    const float* Wproj = (const float*)d_in[3];
    const float* Wg1   = (const float*)d_in[4];
    const float* bg1   = (const float*)d_in[5];
    const float* Wg2   = (const float*)d_in[6];
    const float* bg2   = (const float*)d_in[7];
    const float* Wg3   = (const float*)d_in[8];
    const float* bg3   = (const float*)d_in[9];
    const float* fcW   = (const float*)d_in[10];
    const float* fcb   = (const float*)d_in[11];
    const int*   tspan = (const int*)d_in[12];
    const int*   tran  = (const int*)d_in[13];
    const int*   gspan = (const int*)d_in[14];
    float* out = (float*)d_out;

    float *pt, *pxr, *ptT, *padj, *pWt;
    cudaGetSymbolAddress((void**)&pt, g_t);
    cudaGetSymbolAddress((void**)&pxr, g_xr);
    cudaGetSymbolAddress((void**)&ptT, g_tT);
    cudaGetSymbolAddress((void**)&padj, g_adj);
    cudaGetSymbolAddress((void**)&pWt, g_Wt);

    dim3 gg(6, 64);

    adj_kernel<<<Bn * Nn, 128>>>(dg, dg1);
    span_kernel<<<Bn * Nn, 256>>>(se, tran);
    tmax_kernel<<<Bn, 256>>>(se, tspan);
    wtrans_kernel<<<dim3(24, 24, 4), dim3(32, 8)>>>(Wproj, Wg1, Wg2, Wg3);

    const size_t WSZ = (size_t)Dn * Dn;

    // x = relu(tmps @ W_proj)
    gemm_mma<0, 48><<<gg, 256>>>(pt, pWt + 0 * WSZ, nullptr, Dn, Dn);

    // 3 GCN layers: tT = (x @ Wg)^T ; x += relu(adj @ t / denom + b)
    gemm_mma<1, 48><<<gg, 256>>>(pxr, pWt + 1 * WSZ, nullptr, Dn, Dn);
    gemm_mma<2, 8><<<gg, 256>>>(padj, ptT, bg1, Nn, Nn);
    gemm_mma<1, 48><<<gg, 256>>>(pxr, pWt + 2 * WSZ, nullptr, Dn, Dn);
    gemm_mma<2, 8><<<gg, 256>>>(padj, ptT, bg2, Nn, Nn);
    gemm_mma<1, 48><<<gg, 256>>>(pxr, pWt + 3 * WSZ, nullptr, Dn, Dn);
    gemm_mma<2, 8><<<gg, 256>>>(padj, ptT, bg3, Nn, Nn);

    head_kernel<<<Bn, 256>>>(fcW, fcb, gspan, out);
}

// round 6
// speedup vs baseline: 1.9976x; 1.1991x over previous
#include <cuda_runtime.h>
#include <cstdint>

// Problem constants
#define Bn 64
#define Sn 512
#define Nn 128
#define Dn 768
#define On 3

// Scratch (device globals -- no allocations allowed)
__device__ float g_x[(size_t)Bn * Nn * Dn];      // exact node features (residual stream)
__device__ float g_xr[(size_t)Bn * Nn * Dn];     // tf32-rounded, K-permuted copy (MMA input)
__device__ float g_t[(size_t)Bn * Nn * Dn];      // span sums, rounded+permuted [B*N, D]
__device__ float g_tT[(size_t)Bn * Dn * Nn];     // (x@W)^T per batch, rounded+permuted [B][D][N]
__device__ float g_adj[(size_t)Bn * Nn * Nn];    // clamped adjacency, permuted cols (exact 0/1)
__device__ float g_denom[(size_t)Bn * Nn];       // row-degree + 1e-7
__device__ float g_tmax[(size_t)Bn * Dn];        // target max-pool
__device__ float g_Wt[4 * (size_t)Dn * Dn];      // W^T [N,K], rounded + K-permuted

// ===========================================================================
// helpers
// ===========================================================================
__device__ __forceinline__ uint32_t smem_u32(const void* p) {
    uint32_t a;
    asm("{ .reg .u64 t; cvta.to.shared.u64 t, %1; cvt.u32.u64 %0, t; }" : "=r"(a) : "l"(p));
    return a;
}
__device__ __forceinline__ float f2tf(float f) {
    uint32_t u;
    asm("cvt.rna.tf32.f32 %0, %1;" : "=r"(u) : "f"(f));
    return __uint_as_float(u);
}
// K-permutation within each 16-column group (involution)
__device__ __forceinline__ int permc(int c) {
    return (c & ~15) | ((c & 3) << 2) | ((c >> 2) & 3);
}
#define CP_ASYNC16(dst, src) \
    asm volatile("cp.async.cg.shared.global [%0], [%1], 16;" :: "r"(dst), "l"(src) : "memory")
#define CP_COMMIT() asm volatile("cp.async.commit_group;" ::: "memory")
#define CP_WAIT(n)  asm volatile("cp.async.wait_group %0;" :: "n"(n) : "memory")

__device__ __forceinline__ void mma_tf32(float& c0, float& c1, float& c2, float& c3,
                                         float a0, float a1, float a2, float a3,
                                         float b0, float b1) {
    asm volatile(
        "mma.sync.aligned.m16n8k8.row.col.f32.tf32.tf32.f32 "
        "{%0,%1,%2,%3}, {%4,%5,%6,%7}, {%8,%9}, {%0,%1,%2,%3};"
        : "+f"(c0), "+f"(c1), "+f"(c2), "+f"(c3)
        : "r"(__float_as_uint(a0)), "r"(__float_as_uint(a1)),
          "r"(__float_as_uint(a2)), "r"(__float_as_uint(a3)),
          "r"(__float_as_uint(b0)), "r"(__float_as_uint(b1)));
}

// ===========================================================================
// small prep kernels
// ===========================================================================
__global__ void adj_kernel(const float* __restrict__ dg, const float* __restrict__ dg1) {
    int row = blockIdx.x;
    int tid = threadIdx.x;
    float a = dg[(size_t)row * Nn + tid] + dg1[(size_t)row * Nn + tid];
    a = fminf(a, 1.0f);
    g_adj[(size_t)row * Nn + permc(tid)] = a;
    __shared__ float s[128];
    s[tid] = a;
    __syncthreads();
    #pragma unroll
    for (int st = 64; st > 0; st >>= 1) {
        if (tid < st) s[tid] += s[tid + st];
        __syncthreads();
    }
    if (tid == 0) g_denom[row] = s[0] + 1e-7f;
}

__global__ void span_kernel(const float* __restrict__ se, const int* __restrict__ tran) {
    int row = blockIdx.x;
    int b = row >> 7;
    int s0 = tran[row * 2] + 1;
    int e0 = tran[row * 2 + 1] + 1;
    for (int d = threadIdx.x; d < Dn; d += 256) {
        float acc = 0.0f;
        for (int s = s0; s < e0; ++s)
            acc += se[((size_t)b * Sn + s) * Dn + d];
        g_t[(size_t)row * Dn + permc(d)] = f2tf(acc);
    }
}

__global__ void tmax_kernel(const float* __restrict__ se, const int* __restrict__ tspan) {
    int b = blockIdx.x;
    int l = tspan[b * 2];
    int r = tspan[b * 2 + 1];
    for (int d = threadIdx.x; d < Dn; d += 256) {
        float m = -3.402823466e38f;
        for (int s = l; s < r; ++s)
            m = fmaxf(m, se[((size_t)b * Sn + s) * Dn + d]);
        g_tmax[(size_t)b * Dn + d] = m;
    }
}

// transpose + round + K-permute 4 weight matrices [K=768, N=768] -> g_Wt[w][N][Kperm]
__global__ void wtrans_kernel(const float* __restrict__ W0, const float* __restrict__ W1,
                              const float* __restrict__ W2, const float* __restrict__ W3) {
    __shared__ float t[32][33];
    int w = blockIdx.z;
    const float* W = (w == 0) ? W0 : (w == 1) ? W1 : (w == 2) ? W2 : W3;
    float* O = g_Wt + (size_t)w * Dn * Dn;
    int nx = blockIdx.x * 32;
    int ky = blockIdx.y * 32;
    int tx = threadIdx.x;
    for (int i = threadIdx.y; i < 32; i += 8)
        t[i][tx] = W[(size_t)(ky + i) * Dn + nx + tx];
    __syncthreads();
    for (int i = threadIdx.y; i < 32; i += 8)
        O[(size_t)(nx + i) * Dn + permc(ky + tx)] = f2tf(t[tx][i]);
}

// ===========================================================================
// tf32 mma.sync GEMM: C[M,N] = A[M,K] @ B^T  (B as [N,K]; K pre-permuted, tf32)
// 128x128 block tile, BK=16, 256 threads (8 warps of 64x32)
// 3-stage cp.async pipeline in DYNAMIC shared memory, 2 CTAs/SM
// MODE 0: g_x = relu(acc) (exact) + g_xr rounded/permuted    (proj)
// MODE 1: C^T per-batch store into g_tT (rounded/permuted)   (h@W)
// MODE 2: g_x += relu(acc/denom + bias); g_xr rounded copy   (adjacency)
// ===========================================================================
#define BK 16
#define TSTRIDE 20
#define TILE_F (128 * TSTRIDE)
#define NST 3
#define GEMM_SMEM_BYTES (2 * NST * TILE_F * 4)   // 61440

template <int MODE, int KTILES>
__global__ void __launch_bounds__(256, 2)
gemm_mma(const float* __restrict__ A, const float* __restrict__ B,
         const float* __restrict__ bias, int lda, int ldb) {
    extern __shared__ float smem[];

    int tid = threadIdx.x;
    int lane = tid & 31;
    int warp = tid >> 5;
    int wm = (warp >> 2) * 64;    // warp row base (0/64)
    int wn = (warp & 3) * 32;     // warp col base (0..96)
    int lg = lane >> 2;           // 0..7
    int tg = lane & 3;            // 0..3

    const float* Ab;
    const float* Bb;
    int aRow0, bRow0;
    if (MODE == 2) {
        Ab = A + (size_t)blockIdx.y * Nn * Nn;     // adj[b]
        Bb = B + (size_t)blockIdx.y * Dn * Nn;     // g_tT[b]
        aRow0 = 0;
        bRow0 = blockIdx.x * 128;
    } else {
        Ab = A;
        Bb = B;
        aRow0 = blockIdx.y * 128;
        bRow0 = blockIdx.x * 128;
    }

    float c[4][4][4];
    #pragma unroll
    for (int i = 0; i < 4; ++i)
        #pragma unroll
        for (int j = 0; j < 4; ++j)
            #pragma unroll
            for (int k = 0; k < 4; ++k) c[i][j][k] = 0.0f;

    uint32_t sAbase[NST], sBbase[NST];
    #pragma unroll
    for (int s = 0; s < NST; ++s) {
        sAbase[s] = smem_u32(smem + 2 * s * TILE_F);
        sBbase[s] = smem_u32(smem + (2 * s + 1) * TILE_F);
    }

    auto load_stage = [&](int it, int buf) {
        int k0 = it * BK;
        #pragma unroll
        for (int i = 0; i < 2; ++i) {
            int id = tid + i * 256;
            int row = id >> 2;
            int seg = id & 3;
            CP_ASYNC16(sAbase[buf] + (row * TSTRIDE + seg * 4) * 4,
                       Ab + (size_t)(aRow0 + row) * lda + k0 + seg * 4);
            CP_ASYNC16(sBbase[buf] + (row * TSTRIDE + seg * 4) * 4,
                       Bb + (size_t)(bRow0 + row) * ldb + k0 + seg * 4);
        }
        CP_COMMIT();
    };

    load_stage(0, 0);
    load_stage(1, 1);
    for (int it = 0; it < KTILES; ++it) {
        int buf = it % NST;
        if (it == KTILES - 1) { CP_WAIT(0); } else { CP_WAIT(1); }
        __syncthreads();
        if (it + 2 < KTILES) load_stage(it + 2, (it + 2) % NST);

        const float* as = smem + 2 * buf * TILE_F;
        const float* bs = smem + (2 * buf + 1) * TILE_F;
        // physical cols [4tg..4tg+3] hold logical k = {tg, tg+4, tg+8, tg+12}
        float4 av[4][2], bv[4];
        #pragma unroll
        for (int mi = 0; mi < 4; ++mi) {
            av[mi][0] = *(const float4*)&as[(wm + mi * 16 + lg) * TSTRIDE + 4 * tg];
            av[mi][1] = *(const float4*)&as[(wm + mi * 16 + lg + 8) * TSTRIDE + 4 * tg];
        }
        #pragma unroll
        for (int ni = 0; ni < 4; ++ni)
            bv[ni] = *(const float4*)&bs[(wn + ni * 8 + lg) * TSTRIDE + 4 * tg];
        #pragma unroll
        for (int mi = 0; mi < 4; ++mi)
            #pragma unroll
            for (int ni = 0; ni < 4; ++ni) {
                mma_tf32(c[mi][ni][0], c[mi][ni][1], c[mi][ni][2], c[mi][ni][3],
                         av[mi][0].x, av[mi][1].x, av[mi][0].y, av[mi][1].y,
                         bv[ni].x, bv[ni].y);
                mma_tf32(c[mi][ni][0], c[mi][ni][1], c[mi][ni][2], c[mi][ni][3],
                         av[mi][0].z, av[mi][1].z, av[mi][0].w, av[mi][1].w,
                         bv[ni].z, bv[ni].w);
            }
    }
    __syncthreads();

    // ---- epilogue ----
    if (MODE == 0) {
        size_t row0 = (size_t)blockIdx.y * 128;
        #pragma unroll
        for (int mi = 0; mi < 4; ++mi) {
            int r = wm + mi * 16 + lg;
            #pragma unroll
            for (int ni = 0; ni < 4; ++ni) {
                int cc = blockIdx.x * 128 + wn + ni * 8 + 2 * tg;
                float v0 = fmaxf(c[mi][ni][0], 0.0f);
                float v1 = fmaxf(c[mi][ni][1], 0.0f);
                float v2 = fmaxf(c[mi][ni][2], 0.0f);
                float v3 = fmaxf(c[mi][ni][3], 0.0f);
                g_x[(row0 + r) * Dn + cc]          = v0;
                g_x[(row0 + r) * Dn + cc + 1]      = v1;
                g_x[(row0 + r + 8) * Dn + cc]      = v2;
                g_x[(row0 + r + 8) * Dn + cc + 1]  = v3;
                g_xr[(row0 + r) * Dn + permc(cc)]         = f2tf(v0);
                g_xr[(row0 + r) * Dn + permc(cc + 1)]     = f2tf(v1);
                g_xr[(row0 + r + 8) * Dn + permc(cc)]     = f2tf(v2);
                g_xr[(row0 + r + 8) * Dn + permc(cc + 1)] = f2tf(v3);
            }
        }
    } else if (MODE == 1) {
        int b = blockIdx.y;
        float* outb = g_tT + ((size_t)b * Dn + blockIdx.x * 128) * Nn;
        #pragma unroll
        for (int half = 0; half < 2; ++half) {
            __syncthreads();
            if ((wn >> 6) == half) {
                #pragma unroll
                for (int mi = 0; mi < 4; ++mi) {
                    int r = wm + mi * 16 + lg;
                    #pragma unroll
                    for (int ni = 0; ni < 4; ++ni) {
                        int cl = (wn & 63) + ni * 8 + 2 * tg;
                        smem[cl * 132 + r]           = c[mi][ni][0];
                        smem[(cl + 1) * 132 + r]     = c[mi][ni][1];
                        smem[cl * 132 + r + 8]       = c[mi][ni][2];
                        smem[(cl + 1) * 132 + r + 8] = c[mi][ni][3];
                    }
                }
            }
            __syncthreads();
            // write 64 tT rows (each 128 floats) coalesced; permute K(=node) cols
            for (int i = tid; i < 64 * 32; i += 256) {
                int row = i >> 5;
                int seg = i & 31;
                float4 v;
                v.x = f2tf(smem[row * 132 + permc(seg * 4 + 0)]);
                v.y = f2tf(smem[row * 132 + permc(seg * 4 + 1)]);
                v.z = f2tf(smem[row * 132 + permc(seg * 4 + 2)]);
                v.w = f2tf(smem[row * 132 + permc(seg * 4 + 3)]);
                *(float4*)&outb[(size_t)(half * 64 + row) * Nn + seg * 4] = v;
            }
        }
    } else {
        int b = blockIdx.y;
        #pragma unroll
        for (int mi = 0; mi < 4; ++mi) {
            int r = wm + mi * 16 + lg;
            float id0 = 1.0f / g_denom[b * Nn + r];
            float id1 = 1.0f / g_denom[b * Nn + r + 8];
            size_t row0 = (size_t)(b * Nn + r);
            size_t row1 = row0 + 8;
            #pragma unroll
            for (int ni = 0; ni < 4; ++ni) {
                int cc = blockIdx.x * 128 + wn + ni * 8 + 2 * tg;
                float n0 = g_x[row0 * Dn + cc]     + fmaxf(c[mi][ni][0] * id0 + bias[cc], 0.0f);
                float n1 = g_x[row0 * Dn + cc + 1] + fmaxf(c[mi][ni][1] * id0 + bias[cc + 1], 0.0f);
                float n2 = g_x[row1 * Dn + cc]     + fmaxf(c[mi][ni][2] * id1 + bias[cc], 0.0f);
                float n3 = g_x[row1 * Dn + cc + 1] + fmaxf(c[mi][ni][3] * id1 + bias[cc + 1], 0.0f);
                g_x[row0 * Dn + cc]     = n0;
                g_x[row0 * Dn + cc + 1] = n1;
                g_x[row1 * Dn + cc]     = n2;
                g_x[row1 * Dn + cc + 1] = n3;
                g_xr[row0 * Dn + permc(cc)]     = f2tf(n0);
                g_xr[row0 * Dn + permc(cc + 1)] = f2tf(n1);
                g_xr[row1 * Dn + permc(cc)]     = f2tf(n2);
                g_xr[row1 * Dn + permc(cc + 1)] = f2tf(n3);
            }
        }
    }
}

// ===========================================================================
// head: gcn_target (node-span sum) + concat + fc + tanh
// ===========================================================================
__global__ void head_kernel(const float* __restrict__ fcW, const float* __restrict__ fcb,
                            const int* __restrict__ gspan, float* __restrict__ out) {
    int b = blockIdx.x;
    int tid = threadIdx.x;
    int gs = gspan[b * 2];
    int ge = gspan[b * 2 + 1];
    float p0 = 0.0f, p1 = 0.0f, p2 = 0.0f;
    for (int d = tid; d < Dn; d += 256) {
        float tm = g_tmax[(size_t)b * Dn + d];
        float gt = 0.0f;
        for (int n = gs; n < ge; ++n)
            gt += g_x[((size_t)b * Nn + n) * Dn + d];
        p0 += tm * fcW[d * On + 0] + gt * fcW[(Dn + d) * On + 0];
        p1 += tm * fcW[d * On + 1] + gt * fcW[(Dn + d) * On + 1];
        p2 += tm * fcW[d * On + 2] + gt * fcW[(Dn + d) * On + 2];
    }
    __shared__ float r0[256], r1[256], r2[256];
    r0[tid] = p0; r1[tid] = p1; r2[tid] = p2;
    __syncthreads();
    #pragma unroll
    for (int st = 128; st > 0; st >>= 1) {
        if (tid < st) { r0[tid] += r0[tid + st]; r1[tid] += r1[tid + st]; r2[tid] += r2[tid + st]; }
        __syncthreads();
    }
    if (tid == 0) {
        out[b * On + 0] = tanhf(r0[0] + fcb[0]);
        out[b * On + 1] = tanhf(r1[0] + fcb[1]);
        out[b * On + 2] = tanhf(r2[0] + fcb[2]);
    }
}

// ===========================================================================
extern "C" void kernel_launch(void* const* d_in, const int* in_sizes, int n_in,
                              void* d_out, int out_size) {
    const float* se    = (const float*)d_in[0];
    const float* dg    = (const float*)d_in[1];
    const float* dg1   = (const float*)d_in[2];
    const float* Wproj = (const float*)d_in[3];
    const float* Wg1   = (const float*)d_in[4];
    const float* bg1   = (const float*)d_in[5];
    const float* Wg2   = (const float*)d_in[6];
    const float* bg2   = (const float*)d_in[7];
    const float* Wg3   = (const float*)d_in[8];
    const float* bg3   = (const float*)d_in[9];
    const float* fcW   = (const float*)d_in[10];
    const float* fcb   = (const float*)d_in[11];
    const int*   tspan = (const int*)d_in[12];
    const int*   tran  = (const int*)d_in[13];
    const int*   gspan = (const int*)d_in[14];
    float* out = (float*)d_out;

    float *pt, *pxr, *ptT, *padj, *pWt;
    cudaGetSymbolAddress((void**)&pt, g_t);
    cudaGetSymbolAddress((void**)&pxr, g_xr);
    cudaGetSymbolAddress((void**)&ptT, g_tT);
    cudaGetSymbolAddress((void**)&padj, g_adj);
    cudaGetSymbolAddress((void**)&pWt, g_Wt);

    cudaFuncSetAttribute(gemm_mma<0, 48>, cudaFuncAttributeMaxDynamicSharedMemorySize, GEMM_SMEM_BYTES);
    cudaFuncSetAttribute(gemm_mma<1, 48>, cudaFuncAttributeMaxDynamicSharedMemorySize, GEMM_SMEM_BYTES);
    cudaFuncSetAttribute(gemm_mma<2, 8>,  cudaFuncAttributeMaxDynamicSharedMemorySize, GEMM_SMEM_BYTES);

    dim3 gg(6, 64);

    adj_kernel<<<Bn * Nn, 128>>>(dg, dg1);
    span_kernel<<<Bn * Nn, 256>>>(se, tran);
    tmax_kernel<<<Bn, 256>>>(se, tspan);
    wtrans_kernel<<<dim3(24, 24, 4), dim3(32, 8)>>>(Wproj, Wg1, Wg2, Wg3);

    const size_t WSZ = (size_t)Dn * Dn;

    // x = relu(tmps @ W_proj)
    gemm_mma<0, 48><<<gg, 256, GEMM_SMEM_BYTES>>>(pt, pWt + 0 * WSZ, nullptr, Dn, Dn);

    // 3 GCN layers: tT = (x @ Wg)^T ; x += relu(adj @ t / denom + b)
    gemm_mma<1, 48><<<gg, 256, GEMM_SMEM_BYTES>>>(pxr, pWt + 1 * WSZ, nullptr, Dn, Dn);
    gemm_mma<2, 8><<<gg, 256, GEMM_SMEM_BYTES>>>(padj, ptT, bg1, Nn, Nn);
    gemm_mma<1, 48><<<gg, 256, GEMM_SMEM_BYTES>>>(pxr, pWt + 2 * WSZ, nullptr, Dn, Dn);
    gemm_mma<2, 8><<<gg, 256, GEMM_SMEM_BYTES>>>(padj, ptT, bg2, Nn, Nn);
    gemm_mma<1, 48><<<gg, 256, GEMM_SMEM_BYTES>>>(pxr, pWt + 3 * WSZ, nullptr, Dn, Dn);
    gemm_mma<2, 8><<<gg, 256, GEMM_SMEM_BYTES>>>(padj, ptT, bg3, Nn, Nn);

    head_kernel<<<Bn, 256>>>(fcW, fcb, gspan, out);
}

// round 7
// speedup vs baseline: 2.4677x; 1.2353x over previous
#include <cuda_runtime.h>
#include <cstdint>

// Problem constants
#define Bn 64
#define Sn 512
#define Nn 128
#define Dn 768
#define On 3

// Scratch (device globals -- no allocations allowed)
__device__ float g_x[(size_t)Bn * Nn * Dn];      // exact node features (residual stream)
__device__ float g_xr[(size_t)Bn * Nn * Dn];     // tf32-rounded, K-permuted copy (MMA input)
__device__ float g_t[(size_t)Bn * Nn * Dn];      // span sums, rounded+permuted [B*N, D]
__device__ float g_tT[(size_t)Bn * Dn * Nn];     // (x@W)^T per batch, rounded+permuted [B][D][N]
__device__ float g_adj[(size_t)Bn * Nn * Nn];    // clamped adjacency, permuted cols (exact 0/1)
__device__ float g_denom[(size_t)Bn * Nn];       // row-degree + 1e-7
__device__ float g_tmax[(size_t)Bn * Dn];        // target max-pool
__device__ float g_Wt[4 * (size_t)Dn * Dn];      // W^T [N,K], rounded + K-permuted

// ===========================================================================
// helpers
// ===========================================================================
__device__ __forceinline__ uint32_t smem_u32(const void* p) {
    uint32_t a;
    asm("{ .reg .u64 t; cvta.to.shared.u64 t, %1; cvt.u32.u64 %0, t; }" : "=r"(a) : "l"(p));
    return a;
}
__device__ __forceinline__ float f2tf(float f) {
    uint32_t u;
    asm("cvt.rna.tf32.f32 %0, %1;" : "=r"(u) : "f"(f));
    return __uint_as_float(u);
}
// K-permutation within each 16-column group (involution)
__device__ __forceinline__ int permc(int c) {
    return (c & ~15) | ((c & 3) << 2) | ((c >> 2) & 3);
}
#define CP_ASYNC16(dst, src) \
    asm volatile("cp.async.cg.shared.global [%0], [%1], 16;" :: "r"(dst), "l"(src) : "memory")
#define CP_COMMIT() asm volatile("cp.async.commit_group;" ::: "memory")
#define CP_WAIT(n)  asm volatile("cp.async.wait_group %0;" :: "n"(n) : "memory")

__device__ __forceinline__ void mma_tf32(float& c0, float& c1, float& c2, float& c3,
                                         float a0, float a1, float a2, float a3,
                                         float b0, float b1) {
    asm volatile(
        "mma.sync.aligned.m16n8k8.row.col.f32.tf32.tf32.f32 "
        "{%0,%1,%2,%3}, {%4,%5,%6,%7}, {%8,%9}, {%0,%1,%2,%3};"
        : "+f"(c0), "+f"(c1), "+f"(c2), "+f"(c3)
        : "r"(__float_as_uint(a0)), "r"(__float_as_uint(a1)),
          "r"(__float_as_uint(a2)), "r"(__float_as_uint(a3)),
          "r"(__float_as_uint(b0)), "r"(__float_as_uint(b1)));
}

// ===========================================================================
// small prep kernels
// ===========================================================================
__global__ void adj_kernel(const float* __restrict__ dg, const float* __restrict__ dg1) {
    int row = blockIdx.x;
    int tid = threadIdx.x;
    float a = dg[(size_t)row * Nn + tid] + dg1[(size_t)row * Nn + tid];
    a = fminf(a, 1.0f);
    g_adj[(size_t)row * Nn + permc(tid)] = a;
    __shared__ float s[128];
    s[tid] = a;
    __syncthreads();
    #pragma unroll
    for (int st = 64; st > 0; st >>= 1) {
        if (tid < st) s[tid] += s[tid + st];
        __syncthreads();
    }
    if (tid == 0) g_denom[row] = s[0] + 1e-7f;
}

__global__ void span_kernel(const float* __restrict__ se, const int* __restrict__ tran) {
    int row = blockIdx.x;
    int b = row >> 7;
    int s0 = tran[row * 2] + 1;
    int e0 = tran[row * 2 + 1] + 1;
    for (int d = threadIdx.x; d < Dn; d += 256) {
        float acc = 0.0f;
        for (int s = s0; s < e0; ++s)
            acc += se[((size_t)b * Sn + s) * Dn + d];
        g_t[(size_t)row * Dn + permc(d)] = f2tf(acc);
    }
}

__global__ void tmax_kernel(const float* __restrict__ se, const int* __restrict__ tspan) {
    int b = blockIdx.x;
    int l = tspan[b * 2];
    int r = tspan[b * 2 + 1];
    for (int d = threadIdx.x; d < Dn; d += 256) {
        float m = -3.402823466e38f;
        for (int s = l; s < r; ++s)
            m = fmaxf(m, se[((size_t)b * Sn + s) * Dn + d]);
        g_tmax[(size_t)b * Dn + d] = m;
    }
}

// transpose + round + K-permute 4 weight matrices [K=768, N=768] -> g_Wt[w][N][Kperm]
__global__ void wtrans_kernel(const float* __restrict__ W0, const float* __restrict__ W1,
                              const float* __restrict__ W2, const float* __restrict__ W3) {
    __shared__ float t[32][33];
    int w = blockIdx.z;
    const float* W = (w == 0) ? W0 : (w == 1) ? W1 : (w == 2) ? W2 : W3;
    float* O = g_Wt + (size_t)w * Dn * Dn;
    int nx = blockIdx.x * 32;
    int ky = blockIdx.y * 32;
    int tx = threadIdx.x;
    for (int i = threadIdx.y; i < 32; i += 8)
        t[i][tx] = W[(size_t)(ky + i) * Dn + nx + tx];
    __syncthreads();
    for (int i = threadIdx.y; i < 32; i += 8)
        O[(size_t)(nx + i) * Dn + permc(ky + tx)] = f2tf(t[tx][i]);
}

// ===========================================================================
// tf32 mma.sync GEMM: C[M,N] = A[M,K] @ B^T  (B as [N,K]; K pre-permuted, tf32)
// 128x128 block tile, BK=16, 256 threads (8 warps of 64x32)
// 4-stage cp.async pipeline in dynamic smem (TSTRIDE=16: conflict-free), 2 CTAs/SM
// MODE 0: g_x = relu(acc) (exact) + g_xr rounded/permuted    (proj)
// MODE 1: C^T per-batch store into g_tT (rounded/permuted)   (h@W)
// MODE 2: g_x += relu(acc/denom + bias); g_xr rounded copy   (adjacency)
// ===========================================================================
#define BK 16
#define TSTRIDE 16
#define TILE_F (128 * TSTRIDE)
#define NST 4
#define GEMM_SMEM_BYTES (2 * NST * TILE_F * 4)   // 65536

template <int MODE, int KTILES>
__global__ void __launch_bounds__(256, 2)
gemm_mma(const float* __restrict__ A, const float* __restrict__ B,
         const float* __restrict__ bias, int lda, int ldb) {
    extern __shared__ float smem[];

    int tid = threadIdx.x;
    int lane = tid & 31;
    int warp = tid >> 5;
    int wm = (warp >> 2) * 64;    // warp row base (0/64)
    int wn = (warp & 3) * 32;     // warp col base (0..96)
    int lg = lane >> 2;           // 0..7
    int tg = lane & 3;            // 0..3

    const float* Ab;
    const float* Bb;
    int aRow0, bRow0;
    if (MODE == 2) {
        Ab = A + (size_t)blockIdx.y * Nn * Nn;     // adj[b]
        Bb = B + (size_t)blockIdx.y * Dn * Nn;     // g_tT[b]
        aRow0 = 0;
        bRow0 = blockIdx.x * 128;
    } else {
        Ab = A;
        Bb = B;
        aRow0 = blockIdx.y * 128;
        bRow0 = blockIdx.x * 128;
    }

    float c[4][4][4];
    #pragma unroll
    for (int i = 0; i < 4; ++i)
        #pragma unroll
        for (int j = 0; j < 4; ++j)
            #pragma unroll
            for (int k = 0; k < 4; ++k) c[i][j][k] = 0.0f;

    uint32_t sAbase[NST], sBbase[NST];
    #pragma unroll
    for (int s = 0; s < NST; ++s) {
        sAbase[s] = smem_u32(smem + 2 * s * TILE_F);
        sBbase[s] = smem_u32(smem + (2 * s + 1) * TILE_F);
    }

    auto load_stage = [&](int it, int buf) {
        int k0 = it * BK;
        #pragma unroll
        for (int i = 0; i < 2; ++i) {
            int id = tid + i * 256;
            int row = id >> 2;
            int seg = id & 3;
            CP_ASYNC16(sAbase[buf] + (row * TSTRIDE + seg * 4) * 4,
                       Ab + (size_t)(aRow0 + row) * lda + k0 + seg * 4);
            CP_ASYNC16(sBbase[buf] + (row * TSTRIDE + seg * 4) * 4,
                       Bb + (size_t)(bRow0 + row) * ldb + k0 + seg * 4);
        }
        CP_COMMIT();
    };

    load_stage(0, 0);
    load_stage(1, 1);
    load_stage(2, 2);
    for (int it = 0; it < KTILES; ++it) {
        int buf = it & (NST - 1);
        if (it == KTILES - 1) { CP_WAIT(0); } else { CP_WAIT(2); }
        __syncthreads();
        if (it + 3 < KTILES) load_stage(it + 3, (it + 3) & (NST - 1));

        const float* as = smem + 2 * buf * TILE_F;
        const float* bs = smem + (2 * buf + 1) * TILE_F;
        // physical cols [4tg..4tg+3] hold logical k = {tg, tg+4, tg+8, tg+12}
        float4 av[4][2], bv[4];
        #pragma unroll
        for (int mi = 0; mi < 4; ++mi) {
            av[mi][0] = *(const float4*)&as[(wm + mi * 16 + lg) * TSTRIDE + 4 * tg];
            av[mi][1] = *(const float4*)&as[(wm + mi * 16 + lg + 8) * TSTRIDE + 4 * tg];
        }
        #pragma unroll
        for (int ni = 0; ni < 4; ++ni)
            bv[ni] = *(const float4*)&bs[(wn + ni * 8 + lg) * TSTRIDE + 4 * tg];
        #pragma unroll
        for (int mi = 0; mi < 4; ++mi)
            #pragma unroll
            for (int ni = 0; ni < 4; ++ni) {
                mma_tf32(c[mi][ni][0], c[mi][ni][1], c[mi][ni][2], c[mi][ni][3],
                         av[mi][0].x, av[mi][1].x, av[mi][0].y, av[mi][1].y,
                         bv[ni].x, bv[ni].y);
                mma_tf32(c[mi][ni][0], c[mi][ni][1], c[mi][ni][2], c[mi][ni][3],
                         av[mi][0].z, av[mi][1].z, av[mi][0].w, av[mi][1].w,
                         bv[ni].z, bv[ni].w);
            }
    }
    __syncthreads();

    // ---- epilogue ----
    if (MODE == 0) {
        size_t row0 = (size_t)blockIdx.y * 128;
        #pragma unroll
        for (int mi = 0; mi < 4; ++mi) {
            int r = wm + mi * 16 + lg;
            #pragma unroll
            for (int ni = 0; ni < 4; ++ni) {
                int cc = blockIdx.x * 128 + wn + ni * 8 + 2 * tg;
                float v0 = fmaxf(c[mi][ni][0], 0.0f);
                float v1 = fmaxf(c[mi][ni][1], 0.0f);
                float v2 = fmaxf(c[mi][ni][2], 0.0f);
                float v3 = fmaxf(c[mi][ni][3], 0.0f);
                g_x[(row0 + r) * Dn + cc]          = v0;
                g_x[(row0 + r) * Dn + cc + 1]      = v1;
                g_x[(row0 + r + 8) * Dn + cc]      = v2;
                g_x[(row0 + r + 8) * Dn + cc + 1]  = v3;
                g_xr[(row0 + r) * Dn + permc(cc)]         = f2tf(v0);
                g_xr[(row0 + r) * Dn + permc(cc + 1)]     = f2tf(v1);
                g_xr[(row0 + r + 8) * Dn + permc(cc)]     = f2tf(v2);
                g_xr[(row0 + r + 8) * Dn + permc(cc + 1)] = f2tf(v3);
            }
        }
    } else if (MODE == 1) {
        int b = blockIdx.y;
        float* outb = g_tT + ((size_t)b * Dn + blockIdx.x * 128) * Nn;
        #pragma unroll
        for (int half = 0; half < 2; ++half) {
            __syncthreads();
            if ((wn >> 6) == half) {
                #pragma unroll
                for (int mi = 0; mi < 4; ++mi) {
                    int r = wm + mi * 16 + lg;
                    #pragma unroll
                    for (int ni = 0; ni < 4; ++ni) {
                        int cl = (wn & 63) + ni * 8 + 2 * tg;
                        smem[cl * 132 + r]           = c[mi][ni][0];
                        smem[(cl + 1) * 132 + r]     = c[mi][ni][1];
                        smem[cl * 132 + r + 8]       = c[mi][ni][2];
                        smem[(cl + 1) * 132 + r + 8] = c[mi][ni][3];
                    }
                }
            }
            __syncthreads();
            // write 64 tT rows (each 128 floats) coalesced; permute K(=node) cols
            for (int i = tid; i < 64 * 32; i += 256) {
                int row = i >> 5;
                int seg = i & 31;
                float4 v;
                v.x = f2tf(smem[row * 132 + permc(seg * 4 + 0)]);
                v.y = f2tf(smem[row * 132 + permc(seg * 4 + 1)]);
                v.z = f2tf(smem[row * 132 + permc(seg * 4 + 2)]);
                v.w = f2tf(smem[row * 132 + permc(seg * 4 + 3)]);
                *(float4*)&outb[(size_t)(half * 64 + row) * Nn + seg * 4] = v;
            }
        }
    } else {
        int b = blockIdx.y;
        #pragma unroll
        for (int mi = 0; mi < 4; ++mi) {
            int r = wm + mi * 16 + lg;
            float id0 = 1.0f / g_denom[b * Nn + r];
            float id1 = 1.0f / g_denom[b * Nn + r + 8];
            size_t row0 = (size_t)(b * Nn + r);
            size_t row1 = row0 + 8;
            #pragma unroll
            for (int ni = 0; ni < 4; ++ni) {
                int cc = blockIdx.x * 128 + wn + ni * 8 + 2 * tg;
                float n0 = g_x[row0 * Dn + cc]     + fmaxf(c[mi][ni][0] * id0 + bias[cc], 0.0f);
                float n1 = g_x[row0 * Dn + cc + 1] + fmaxf(c[mi][ni][1] * id0 + bias[cc + 1], 0.0f);
                float n2 = g_x[row1 * Dn + cc]     + fmaxf(c[mi][ni][2] * id1 + bias[cc], 0.0f);
                float n3 = g_x[row1 * Dn + cc + 1] + fmaxf(c[mi][ni][3] * id1 + bias[cc + 1], 0.0f);
                g_x[row0 * Dn + cc]     = n0;
                g_x[row0 * Dn + cc + 1] = n1;
                g_x[row1 * Dn + cc]     = n2;
                g_x[row1 * Dn + cc + 1] = n3;
                g_xr[row0 * Dn + permc(cc)]     = f2tf(n0);
                g_xr[row0 * Dn + permc(cc + 1)] = f2tf(n1);
                g_xr[row1 * Dn + permc(cc)]     = f2tf(n2);
                g_xr[row1 * Dn + permc(cc + 1)] = f2tf(n3);
            }
        }
    }
}

// ===========================================================================
// head: gcn_target (node-span sum) + concat + fc + tanh
// ===========================================================================
__global__ void head_kernel(const float* __restrict__ fcW, const float* __restrict__ fcb,
                            const int* __restrict__ gspan, float* __restrict__ out) {
    int b = blockIdx.x;
    int tid = threadIdx.x;
    int gs = gspan[b * 2];
    int ge = gspan[b * 2 + 1];
    float p0 = 0.0f, p1 = 0.0f, p2 = 0.0f;
    for (int d = tid; d < Dn; d += 256) {
        float tm = g_tmax[(size_t)b * Dn + d];
        float gt = 0.0f;
        for (int n = gs; n < ge; ++n)
            gt += g_x[((size_t)b * Nn + n) * Dn + d];
        p0 += tm * fcW[d * On + 0] + gt * fcW[(Dn + d) * On + 0];
        p1 += tm * fcW[d * On + 1] + gt * fcW[(Dn + d) * On + 1];
        p2 += tm * fcW[d * On + 2] + gt * fcW[(Dn + d) * On + 2];
    }
    __shared__ float r0[256], r1[256], r2[256];
    r0[tid] = p0; r1[tid] = p1; r2[tid] = p2;
    __syncthreads();
    #pragma unroll
    for (int st = 128; st > 0; st >>= 1) {
        if (tid < st) { r0[tid] += r0[tid + st]; r1[tid] += r1[tid + st]; r2[tid] += r2[tid + st]; }
        __syncthreads();
    }
    if (tid == 0) {
        out[b * On + 0] = tanhf(r0[0] + fcb[0]);
        out[b * On + 1] = tanhf(r1[0] + fcb[1]);
        out[b * On + 2] = tanhf(r2[0] + fcb[2]);
    }
}

// ===========================================================================
extern "C" void kernel_launch(void* const* d_in, const int* in_sizes, int n_in,
                              void* d_out, int out_size) {
    const float* se    = (const float*)d_in[0];
    const float* dg    = (const float*)d_in[1];
    const float* dg1   = (const float*)d_in[2];
    const float* Wproj = (const float*)d_in[3];
    const float* Wg1   = (const float*)d_in[4];
    const float* bg1   = (const float*)d_in[5];
    const float* Wg2   = (const float*)d_in[6];
    const float* bg2   = (const float*)d_in[7];
    const float* Wg3   = (const float*)d_in[8];
    const float* bg3   = (const float*)d_in[9];
    const float* fcW   = (const float*)d_in[10];
    const float* fcb   = (const float*)d_in[11];
    const int*   tspan = (const int*)d_in[12];
    const int*   tran  = (const int*)d_in[13];
    const int*   gspan = (const int*)d_in[14];
    float* out = (float*)d_out;

    float *pt, *pxr, *ptT, *padj, *pWt;
    cudaGetSymbolAddress((void**)&pt, g_t);
    cudaGetSymbolAddress((void**)&pxr, g_xr);
    cudaGetSymbolAddress((void**)&ptT, g_tT);
    cudaGetSymbolAddress((void**)&padj, g_adj);
    cudaGetSymbolAddress((void**)&pWt, g_Wt);

    cudaFuncSetAttribute(gemm_mma<0, 48>, cudaFuncAttributeMaxDynamicSharedMemorySize, GEMM_SMEM_BYTES);
    cudaFuncSetAttribute(gemm_mma<1, 48>, cudaFuncAttributeMaxDynamicSharedMemorySize, GEMM_SMEM_BYTES);
    cudaFuncSetAttribute(gemm_mma<2, 8>,  cudaFuncAttributeMaxDynamicSharedMemorySize, GEMM_SMEM_BYTES);

    dim3 gg(6, 64);

    adj_kernel<<<Bn * Nn, 128>>>(dg, dg1);
    span_kernel<<<Bn * Nn, 256>>>(se, tran);
    tmax_kernel<<<Bn, 256>>>(se, tspan);
    wtrans_kernel<<<dim3(24, 24, 4), dim3(32, 8)>>>(Wproj, Wg1, Wg2, Wg3);

    const size_t WSZ = (size_t)Dn * Dn;

    // x = relu(tmps @ W_proj)
    gemm_mma<0, 48><<<gg, 256, GEMM_SMEM_BYTES>>>(pt, pWt + 0 * WSZ, nullptr, Dn, Dn);

    // 3 GCN layers: tT = (x @ Wg)^T ; x += relu(adj @ t / denom + b)
    gemm_mma<1, 48><<<gg, 256, GEMM_SMEM_BYTES>>>(pxr, pWt + 1 * WSZ, nullptr, Dn, Dn);
    gemm_mma<2, 8><<<gg, 256, GEMM_SMEM_BYTES>>>(padj, ptT, bg1, Nn, Nn);
    gemm_mma<1, 48><<<gg, 256, GEMM_SMEM_BYTES>>>(pxr, pWt + 2 * WSZ, nullptr, Dn, Dn);
    gemm_mma<2, 8><<<gg, 256, GEMM_SMEM_BYTES>>>(padj, ptT, bg2, Nn, Nn);
    gemm_mma<1, 48><<<gg, 256, GEMM_SMEM_BYTES>>>(pxr, pWt + 3 * WSZ, nullptr, Dn, Dn);
    gemm_mma<2, 8><<<gg, 256, GEMM_SMEM_BYTES>>>(padj, ptT, bg3, Nn, Nn);

    head_kernel<<<Bn, 256>>>(fcW, fcb, gspan, out);
}